// round 14
// baseline (speedup 1.0000x reference)
#include <cuda_runtime.h>
#include <cstdint>

#define BROWS 8192
#define KDIM  2048
#define NDIM  3072
#define NSUBJ 8

#define TM 128
#define TN 128
#define KC 32                      // K floats per stage
#define KITERS (KDIM/KC)           // 64
#define STAGES 3
#define NT_N (NDIM/TN)             // 24
#define MAXMT 72
#define NTHR 256                   // 8 warps: 2 (m) x 4 (n), warp tile 64x32
#define GP   304                   // persistent grid: 2 CTAs x 152 SMs

// ---- shared memory layout (bytes) ----
#define SM_ROWS 0                  // 128 ints: [0,512)
#define SM_BIAS 512                // 128 floats: [512,1024)
#define SM_MBARF 1024              // 3 full mbarriers * 8B: [1024,1048)
#define SM_NEXT 1048               // next tile idx (1 int): [1048,1052)
#define SM_A    1056               // 16B aligned
#define A_ST    16384              // 128x32 floats, interleaved, pre-tf32
#define SM_B    (SM_A + STAGES*A_ST)     // 50208
#define B_ROW   132                // 128 + 4 pad floats per k-row (528B)
#define B_ST    (KC*B_ROW*4)       // 16896
#define SMEM_BYTES (SM_B + STAGES*B_ST)  // 100896  (2 CTAs/SM fit)
#define STAGE_BYTES (A_ST + KC*512)      // 32768 tx bytes

// ---- device scratch ----
__device__ int g_rowlist[BROWS + NSUBJ*TM];
__device__ int g_tsubj[MAXMT];
__device__ int g_tbase[MAXMT];
__device__ int g_ntiles;
__device__ int g_ctr;              // dynamic tile counter
// A staged: per (m-tile, k-stage) 16KB interleaved, pre-tf32. 72MB.
__device__ float g_xstage[MAXMT * KITERS * (TM * KC)];

static __device__ __forceinline__ uint32_t smem_u32(const void* p) {
    uint32_t a;
    asm("{ .reg .u64 t; cvta.to.shared.u64 t, %1; cvt.u32.u64 %0, t; }"
        : "=r"(a) : "l"(p));
    return a;
}
static __device__ __forceinline__ uint32_t f2tf(float f) {
    uint32_t r;
    asm("cvt.rna.tf32.f32 %0, %1;" : "=r"(r) : "f"(f));
    return r;
}
static __device__ __forceinline__ void mma8(float* c, const uint32_t* a,
                                            uint32_t b0, uint32_t b1) {
    asm volatile(
        "mma.sync.aligned.m16n8k8.row.col.f32.tf32.tf32.f32 "
        "{%0,%1,%2,%3}, {%4,%5,%6,%7}, {%8,%9}, {%0,%1,%2,%3};"
        : "+f"(c[0]), "+f"(c[1]), "+f"(c[2]), "+f"(c[3])
        : "r"(a[0]), "r"(a[1]), "r"(a[2]), "r"(a[3]), "r"(b0), "r"(b1));
}
static __device__ __forceinline__ void bulk_g2s(uint32_t dst, const void* src,
                                                uint32_t bytes, uint32_t mbar) {
    asm volatile(
        "cp.async.bulk.shared::cluster.global.mbarrier::complete_tx::bytes "
        "[%0], [%1], %2, [%3];"
        :: "r"(dst), "l"(src), "r"(bytes), "r"(mbar) : "memory");
}
#define MBARRIER_INIT(mb, cnt) \
    asm volatile("mbarrier.init.shared.b64 [%0], %1;" \
                 :: "r"((uint32_t)(mb)), "r"((uint32_t)(cnt)) : "memory")
#define MBARRIER_EXPECT_TX(mb, tx) \
    asm volatile("mbarrier.arrive.expect_tx.shared.b64 _, [%0], %1;" \
                 :: "r"((uint32_t)(mb)), "r"((uint32_t)(tx)) : "memory")
#define MBARRIER_WAIT_PARITY(mb, par) do {                                         \
    uint32_t _mb = (uint32_t)(mb), _pr = (uint32_t)(par), _dn;                     \
    asm volatile("{\n\t.reg .pred p;\n\t"                                          \
        "mbarrier.try_wait.parity.acquire.cta.shared::cta.b64 p, [%1], %2;\n\t"    \
        "selp.b32 %0, 1, 0, p;\n\t}"                                               \
        : "=r"(_dn) : "r"(_mb), "r"(_pr) : "memory");                              \
    if (!_dn) {                                                                    \
        asm volatile("{\n\t.reg .pred P1;\n\t"                                     \
        "WL_%=:\n\t"                                                               \
        "mbarrier.try_wait.parity.acquire.cta.shared::cta.b64 P1, [%0], %1, 0x989680;\n\t" \
        "@P1 bra.uni WD_%=;\n\t"                                                   \
        "bra.uni WL_%=;\n\t"                                                       \
        "WD_%=:\n\t}" :: "r"(_mb), "r"(_pr) : "memory");                           \
    }                                                                              \
} while (0)

// ---------- kernel 1: stable counting sort of rows by subject (1024 thr) ----------
__global__ void bucket_kernel(const int* __restrict__ sids) {
    __shared__ int wtot[32][NSUBJ];
    __shared__ int wexc[32][NSUBJ];
    __shared__ int tot[NSUBJ], offp[NSUBJ];
    const int t = threadIdx.x;
    const int w = t >> 5, ln = t & 31;
    if (t == 0) g_ctr = GP;        // reset dynamic tile counter each launch
    int loc[NSUBJ];
    int sv[8];
#pragma unroll
    for (int s = 0; s < NSUBJ; s++) loc[s] = 0;
    const int base = t * 8;
#pragma unroll
    for (int i = 0; i < 8; i++) {
        int s = sids[base + i] & 7;
        sv[i] = s;
        loc[s]++;
    }
    int exc[NSUBJ];
#pragma unroll
    for (int s = 0; s < NSUBJ; s++) {
        int sc = loc[s];
#pragma unroll
        for (int d = 1; d < 32; d <<= 1) {
            int o = __shfl_up_sync(0xffffffffu, sc, d);
            if (ln >= d) sc += o;
        }
        exc[s] = sc - loc[s];
        int tw = __shfl_sync(0xffffffffu, sc, 31);
        if (ln == 0) wtot[w][s] = tw;
    }
    __syncthreads();
    if (w < NSUBJ) {
        int v = wtot[ln][w];
        int sc = v;
#pragma unroll
        for (int d = 1; d < 32; d <<= 1) {
            int o = __shfl_up_sync(0xffffffffu, sc, d);
            if (ln >= d) sc += o;
        }
        wexc[ln][w] = sc - v;
        if (ln == 31) tot[w] = sc;
    }
    __syncthreads();
    if (t == 0) {
        int off = 0, ntl = 0;
        for (int s = 0; s < NSUBJ; s++) {
            offp[s] = off;
            int c = tot[s];
            int ntiles = (c + TM - 1) / TM;
            for (int j = 0; j < ntiles; j++) {
                g_tsubj[ntl] = s;
                g_tbase[ntl] = off + j * TM;
                ntl++;
            }
            off += ntiles * TM;
        }
        g_ntiles = ntl;
    }
    __syncthreads();
    if (w < NSUBJ) {
        int s = w, c = tot[s];
        int pad = ((c + TM - 1) / TM) * TM;
        for (int j = c + ln; j < pad; j += 32) g_rowlist[offp[s] + j] = -1;
    }
    int p[NSUBJ];
#pragma unroll
    for (int s = 0; s < NSUBJ; s++) p[s] = offp[s] + wexc[w][s] + exc[s];
#pragma unroll
    for (int i = 0; i < 8; i++) {
        int s = sv[i];
        g_rowlist[p[s]++] = base + i;
    }
}

// ---------- kernel 1b: gather + pre-convert A (interleaved layout) ----------
__global__ void gather_kernel(const float* __restrict__ x) {
    const int mt = blockIdx.y;
    if (mt >= g_ntiles) return;
    const int ks = blockIdx.x;
    __shared__ int rows[TM];
    const int t = threadIdx.x;
    if (t < TM) {
        int r = g_rowlist[g_tbase[mt] + t];
        rows[t] = (r < 0) ? 0 : r;
    }
    __syncthreads();
    const int row = t >> 3, k4 = t & 7;
    const float* src = x + (size_t)rows[row] * KDIM + ks * KC + k4 * 4;
    float4 v = *(const float4*)src;
    uint4 q;
    q.x = f2tf(v.x);
    q.y = f2tf(v.y);
    q.z = f2tf(v.z);
    q.w = f2tf(v.w);
    float* dst = g_xstage + (size_t)(mt * KITERS + ks) * (TM * KC);
    *(uint4*)(dst + (k4 >> 1) * 1024 + (k4 & 1) * 512 + row * 4) = q;
}

// ---------- kernel 2: persistent tf32 mma.sync GEMM, dynamic tiles ----------
__global__ void __launch_bounds__(NTHR, 2) gemm_kernel(
    const float* __restrict__ w, const float* __restrict__ bias,
    float* __restrict__ out)
{
    extern __shared__ char smem[];
    int* rows = (int*)(smem + SM_ROWS);
    float* bsm = (float*)(smem + SM_BIAS);
    int* nextp = (int*)(smem + SM_NEXT);
    const float* As = (const float*)(smem + SM_A);
    const float* Bs = (const float*)(smem + SM_B);

    const int t = threadIdx.x;
    const int wid = t >> 5, lane = t & 31;
    const uint32_t sb = smem_u32(smem);
    const int TT = g_ntiles * NT_N;
    int cur = blockIdx.x;
    if (cur >= TT) return;

    if (t == 0) {
        for (int s = 0; s < STAGES; s++) MBARRIER_INIT(sb + SM_MBARF + s * 8, 1);
        asm volatile("fence.proxy.async.shared::cta;" ::: "memory");
    }
    __syncthreads();

    // fill stage ks of tile tidx into slot fslot (warp 0 collective)
    auto fill = [&](int tidx, int ks, int fslot) {
        const int mt = tidx / NT_N, nt2 = tidx - mt * NT_N;
        const int subj = g_tsubj[mt];
        const float* ast = g_xstage + (size_t)(mt * KITERS + ks) * (TM * KC);
        const float* wb = w + (size_t)subj * KDIM * NDIM +
                          (size_t)(ks * KC) * NDIM + nt2 * TN;
        uint32_t mbar = sb + SM_MBARF + fslot * 8;
        if (lane == 0) {
            MBARRIER_EXPECT_TX(mbar, STAGE_BYTES);
            bulk_g2s(sb + SM_A + fslot * A_ST, ast, A_ST, mbar);
        }
        bulk_g2s(sb + SM_B + fslot * B_ST + lane * (B_ROW * 4),
                 wb + (size_t)lane * NDIM, 512, mbar);
    };

    if (wid == 0) {
        fill(cur, 0, 0);
        fill(cur, 1, 1);
    }

    // warp grid 2 (m) x 4 (n); warp tile 64 x 32
    const int wm = wid & 1, wn = wid >> 1;
    const int gid = lane >> 2, tig = lane & 3;
    const int aBase = wm * 256 + lane;                  // uint idx
    const int bBase = tig * B_ROW + wn * 32 + gid;      // float idx

    int slot = 0, par = 0, fslot = 2;

#pragma unroll 1
    while (cur < TT) {
        const int mt = cur / NT_N, nt2 = cur - mt * NT_N;
        const int n0 = nt2 * TN;
        const int subj = g_tsubj[mt];
        const int rowbase = g_tbase[mt];
        if (t < 128) {
            rows[t] = g_rowlist[rowbase + t];
            bsm[t] = bias[(size_t)subj * NDIM + n0 + t];
        }
        if (t == 0) nextp[0] = atomicAdd(&g_ctr, 1);    // claim next tile now
        __syncthreads();
        const int nxt = nextp[0];

        float acc[4][4][4];
#pragma unroll
        for (int m = 0; m < 4; m++)
#pragma unroll
            for (int n = 0; n < 4; n++)
#pragma unroll
                for (int q = 0; q < 4; q++) acc[m][n][q] = 0.0f;

#pragma unroll 1
        for (int i = 0; i < KITERS; i++) {
            __syncthreads();   // all warps done reading the slot fill targets
            if (wid == 0) {
                int fs = i + 2;
                if (fs < KITERS) fill(cur, fs, fslot);
                else if (nxt < TT) fill(nxt, fs - KITERS, fslot);
                fslot = (fslot == 2) ? 0 : fslot + 1;
            }
            MBARRIER_WAIT_PARITY(sb + SM_MBARF + slot * 8, par);

            const uint32_t* Au = (const uint32_t*)(As + slot * (A_ST / 4));
            const float* Bst = Bs + slot * (B_ST / 4);
#pragma unroll
            for (int kb = 0; kb < 4; kb++) {
                uint32_t a[4][4];
#pragma unroll
                for (int m = 0; m < 4; m++) {
                    const uint32_t* p = Au + kb * 1024 + aBase + m * 64;
                    a[m][0] = p[0];
                    a[m][1] = p[32];
                    a[m][2] = p[512];
                    a[m][3] = p[544];
                }
                uint32_t b0[4], b1[4];
#pragma unroll
                for (int n = 0; n < 4; n++) {
                    const float* p = Bst + kb * (8 * B_ROW) + bBase + n * 8;
                    b0[n] = f2tf(p[0]);
                    b1[n] = f2tf(p[4 * B_ROW]);
                }
#pragma unroll
                for (int m = 0; m < 4; m++)
#pragma unroll
                    for (int n = 0; n < 4; n++)
                        mma8(acc[m][n], a[m], b0[n], b1[n]);
            }
            slot++;
            if (slot == STAGES) { slot = 0; par ^= 1; }
        }

        // ---- epilogue: add bias, scatter rows ----
#pragma unroll
        for (int m = 0; m < 4; m++) {
            int r0 = wm * 64 + m * 16 + gid;
            int ra = rows[r0], rb = rows[r0 + 8];
#pragma unroll
            for (int n = 0; n < 4; n++) {
                int lc = wn * 32 + n * 8 + tig * 2;
                float bv0 = bsm[lc], bv1 = bsm[lc + 1];
                if (ra >= 0) {
                    float2 v = make_float2(acc[m][n][0] + bv0, acc[m][n][1] + bv1);
                    *(float2*)(out + (size_t)ra * NDIM + n0 + lc) = v;
                }
                if (rb >= 0) {
                    float2 v = make_float2(acc[m][n][2] + bv0, acc[m][n][3] + bv1);
                    *(float2*)(out + (size_t)rb * NDIM + n0 + lc) = v;
                }
            }
        }
        __syncthreads();   // epilogue reads of rows/bsm done before next tile
        cur = nxt;
    }
}

extern "C" void kernel_launch(void* const* d_in, const int* in_sizes, int n_in,
                              void* d_out, int out_size) {
    const float* x = (const float*)d_in[0];
    const int* sid = (const int*)d_in[1];
    const float* w = (const float*)d_in[2];
    const float* b = (const float*)d_in[3];
    float* out = (float*)d_out;

    cudaFuncSetAttribute(gemm_kernel,
                         cudaFuncAttributeMaxDynamicSharedMemorySize, SMEM_BYTES);
    bucket_kernel<<<1, 1024>>>(sid);
    dim3 ggrid(KITERS, MAXMT);
    gather_kernel<<<ggrid, 1024>>>(x);
    gemm_kernel<<<GP, NTHR, SMEM_BYTES>>>(w, b, out);
}

// round 15
// speedup vs baseline: 1.1360x; 1.1360x over previous
#include <cuda_runtime.h>
#include <cstdint>

#define BROWS 8192
#define KDIM  2048
#define NDIM  3072
#define NSUBJ 8

#define TM 128
#define TN 128
#define KC 32                      // K floats per stage
#define KITERS (KDIM/KC)           // 64
#define STAGES 3
#define NT_N (NDIM/TN)             // 24
#define MAXMT 72
#define NTHR 256                   // 8 warps: 2 (m) x 4 (n), warp tile 64x32

// ---- shared memory layout (bytes) ----
#define SM_ROWS 0                  // 128 ints: [0,512)
#define SM_BIAS 512                // 128 floats: [512,1024)
#define SM_MBARF 1024              // 3 full mbarriers * 8B: [1024,1048)
#define SM_A    1056               // 16B aligned
#define A_ST    16384              // 128x32 floats, fragment-packed, pre-tf32
#define SM_B    (SM_A + STAGES*A_ST)     // 50208
#define B_ROW   132                // 128 + 4 pad floats per k-row (528B)
#define B_ST    (KC*B_ROW*4)       // 16896
#define SMEM_BYTES (SM_B + STAGES*B_ST)  // 100896  (2 CTAs/SM fit)
#define STAGE_BYTES (A_ST + KC*512)      // 32768 tx bytes

// ---- device scratch ----
__device__ int g_rowlist[BROWS + NSUBJ*TM];
__device__ int g_tsubj[MAXMT];
__device__ int g_tbase[MAXMT];
__device__ int g_ntiles;
// A staged: per (m-tile, k-stage) 16KB fragment-packed, pre-tf32. 72MB.
__device__ float g_xstage[MAXMT * KITERS * (TM * KC)];

static __device__ __forceinline__ uint32_t smem_u32(const void* p) {
    uint32_t a;
    asm("{ .reg .u64 t; cvta.to.shared.u64 t, %1; cvt.u32.u64 %0, t; }"
        : "=r"(a) : "l"(p));
    return a;
}
static __device__ __forceinline__ uint32_t f2tf(float f) {
    uint32_t r;
    asm("cvt.rna.tf32.f32 %0, %1;" : "=r"(r) : "f"(f));
    return r;
}
static __device__ __forceinline__ void mma8(float* c, const uint32_t* a,
                                            uint32_t b0, uint32_t b1) {
    asm volatile(
        "mma.sync.aligned.m16n8k8.row.col.f32.tf32.tf32.f32 "
        "{%0,%1,%2,%3}, {%4,%5,%6,%7}, {%8,%9}, {%0,%1,%2,%3};"
        : "+f"(c[0]), "+f"(c[1]), "+f"(c[2]), "+f"(c[3])
        : "r"(a[0]), "r"(a[1]), "r"(a[2]), "r"(a[3]), "r"(b0), "r"(b1));
}
static __device__ __forceinline__ void bulk_g2s(uint32_t dst, const void* src,
                                                uint32_t bytes, uint32_t mbar) {
    asm volatile(
        "cp.async.bulk.shared::cluster.global.mbarrier::complete_tx::bytes "
        "[%0], [%1], %2, [%3];"
        :: "r"(dst), "l"(src), "r"(bytes), "r"(mbar) : "memory");
}
#define MBARRIER_INIT(mb, cnt) \
    asm volatile("mbarrier.init.shared.b64 [%0], %1;" \
                 :: "r"((uint32_t)(mb)), "r"((uint32_t)(cnt)) : "memory")
#define MBARRIER_EXPECT_TX(mb, tx) \
    asm volatile("mbarrier.arrive.expect_tx.shared.b64 _, [%0], %1;" \
                 :: "r"((uint32_t)(mb)), "r"((uint32_t)(tx)) : "memory")
#define MBARRIER_WAIT_PARITY(mb, par) do {                                         \
    uint32_t _mb = (uint32_t)(mb), _pr = (uint32_t)(par), _dn;                     \
    asm volatile("{\n\t.reg .pred p;\n\t"                                          \
        "mbarrier.try_wait.parity.acquire.cta.shared::cta.b64 p, [%1], %2;\n\t"    \
        "selp.b32 %0, 1, 0, p;\n\t}"                                               \
        : "=r"(_dn) : "r"(_mb), "r"(_pr) : "memory");                              \
    if (!_dn) {                                                                    \
        asm volatile("{\n\t.reg .pred P1;\n\t"                                     \
        "WL_%=:\n\t"                                                               \
        "mbarrier.try_wait.parity.acquire.cta.shared::cta.b64 P1, [%0], %1, 0x989680;\n\t" \
        "@P1 bra.uni WD_%=;\n\t"                                                   \
        "bra.uni WL_%=;\n\t"                                                       \
        "WD_%=:\n\t}" :: "r"(_mb), "r"(_pr) : "memory");                           \
    }                                                                              \
} while (0)

// ---------- kernel 1: stable counting sort of rows by subject (1024 thr) ----------
__global__ void bucket_kernel(const int* __restrict__ sids) {
    __shared__ int wtot[32][NSUBJ];
    __shared__ int wexc[32][NSUBJ];
    __shared__ int tot[NSUBJ], offp[NSUBJ];
    const int t = threadIdx.x;
    const int w = t >> 5, ln = t & 31;
    int loc[NSUBJ];
    int sv[8];
#pragma unroll
    for (int s = 0; s < NSUBJ; s++) loc[s] = 0;
    const int base = t * 8;
#pragma unroll
    for (int i = 0; i < 8; i++) {
        int s = sids[base + i] & 7;
        sv[i] = s;
        loc[s]++;
    }
    int exc[NSUBJ];
#pragma unroll
    for (int s = 0; s < NSUBJ; s++) {
        int sc = loc[s];
#pragma unroll
        for (int d = 1; d < 32; d <<= 1) {
            int o = __shfl_up_sync(0xffffffffu, sc, d);
            if (ln >= d) sc += o;
        }
        exc[s] = sc - loc[s];
        int tw = __shfl_sync(0xffffffffu, sc, 31);
        if (ln == 0) wtot[w][s] = tw;
    }
    __syncthreads();
    if (w < NSUBJ) {
        int v = wtot[ln][w];
        int sc = v;
#pragma unroll
        for (int d = 1; d < 32; d <<= 1) {
            int o = __shfl_up_sync(0xffffffffu, sc, d);
            if (ln >= d) sc += o;
        }
        wexc[ln][w] = sc - v;
        if (ln == 31) tot[w] = sc;
    }
    __syncthreads();
    if (t == 0) {
        int off = 0, ntl = 0;
        for (int s = 0; s < NSUBJ; s++) {
            offp[s] = off;
            int c = tot[s];
            int ntiles = (c + TM - 1) / TM;
            for (int j = 0; j < ntiles; j++) {
                g_tsubj[ntl] = s;
                g_tbase[ntl] = off + j * TM;
                ntl++;
            }
            off += ntiles * TM;
        }
        g_ntiles = ntl;
    }
    __syncthreads();
    if (w < NSUBJ) {
        int s = w, c = tot[s];
        int pad = ((c + TM - 1) / TM) * TM;
        for (int j = c + ln; j < pad; j += 32) g_rowlist[offp[s] + j] = -1;
    }
    int p[NSUBJ];
#pragma unroll
    for (int s = 0; s < NSUBJ; s++) p[s] = offp[s] + wexc[w][s] + exc[s];
#pragma unroll
    for (int i = 0; i < 8; i++) {
        int s = sv[i];
        g_rowlist[p[s]++] = base + i;
    }
}

// ---------- kernel 1b: gather + pre-convert + fragment-pack A ----------
// Block = one (mt, ks) stage: 1024 threads, thread = (m16, kb, lane).
// Quad = {a0,a1,a2,a3}: a0=A[m16*16+gid][kb*8+tig], a1=+8 row, a2=+4 col, a3=both.
__global__ void gather_kernel(const float* __restrict__ x) {
    const int mt = blockIdx.y;
    if (mt >= g_ntiles) return;
    const int ks = blockIdx.x;
    __shared__ int rows[TM];
    const int t = threadIdx.x;
    if (t < TM) {
        int r = g_rowlist[g_tbase[mt] + t];
        rows[t] = (r < 0) ? 0 : r;
    }
    __syncthreads();
    const int lane = t & 31, kb = (t >> 5) & 3, m16 = t >> 7;
    const int gid = lane >> 2, tig = lane & 3;
    const int ra = rows[m16 * 16 + gid], rb = rows[m16 * 16 + gid + 8];
    const float* pa = x + (size_t)ra * KDIM + ks * KC + kb * 8 + tig;
    const float* pb = x + (size_t)rb * KDIM + ks * KC + kb * 8 + tig;
    uint4 q;
    q.x = f2tf(pa[0]);
    q.y = f2tf(pb[0]);
    q.z = f2tf(pa[4]);
    q.w = f2tf(pb[4]);
    float* dst = g_xstage + (size_t)(mt * KITERS + ks) * (TM * KC);
    *(uint4*)(dst + ((m16 * 4 + kb) * 32 + lane) * 4) = q;
}

// ---------- kernel 2: tf32 mma.sync GEMM, 2 CTAs/SM, packed-A LDS.128 ----------
__global__ void __launch_bounds__(NTHR, 2) gemm_kernel(
    const float* __restrict__ w, const float* __restrict__ bias,
    float* __restrict__ out)
{
    const int mt = blockIdx.y;
    if (mt >= g_ntiles) return;
    extern __shared__ char smem[];
    int* rows = (int*)(smem + SM_ROWS);
    float* bsm = (float*)(smem + SM_BIAS);
    const float* As = (const float*)(smem + SM_A);
    const float* Bs = (const float*)(smem + SM_B);

    const int t = threadIdx.x;
    const int wid = t >> 5, lane = t & 31;
    const uint32_t sb = smem_u32(smem);
    const int subj = g_tsubj[mt];
    const int rowbase = g_tbase[mt];
    const int n0 = blockIdx.x * TN;

    if (t < 128) {
        rows[t] = g_rowlist[rowbase + t];
        bsm[t] = bias[(size_t)subj * NDIM + n0 + t];
    }
    if (t == 0) {
        for (int s = 0; s < STAGES; s++) MBARRIER_INIT(sb + SM_MBARF + s * 8, 1);
        asm volatile("fence.proxy.async.shared::cta;" ::: "memory");
    }
    __syncthreads();

    const float* astage = g_xstage + (size_t)mt * KITERS * (TM * KC);
    const float* wbase = w + (size_t)subj * KDIM * NDIM + n0;

    // warp 0 fills stage ks into the given slot: 1 bulk A + 32 bulks B (512B)
    auto bulk_fill = [&](int ks, int fslot) {
        uint32_t mbar = sb + SM_MBARF + fslot * 8;
        if (lane == 0) {
            MBARRIER_EXPECT_TX(mbar, STAGE_BYTES);
            bulk_g2s(sb + SM_A + fslot * A_ST, astage + (size_t)ks * (TM * KC),
                     A_ST, mbar);
        }
        bulk_g2s(sb + SM_B + fslot * B_ST + lane * (B_ROW * 4),
                 wbase + (size_t)(ks * KC + lane) * NDIM, 512, mbar);
    };

    if (wid == 0) {
        bulk_fill(0, 0);
        bulk_fill(1, 1);
    }

    // warp grid 2 (m) x 4 (n); warp tile 64 x 32
    const int wm = wid & 1, wn = wid >> 1;
    const int gid = lane >> 2, tig = lane & 3;

    float acc[4][4][4];
#pragma unroll
    for (int m = 0; m < 4; m++)
#pragma unroll
        for (int n = 0; n < 4; n++)
#pragma unroll
            for (int q = 0; q < 4; q++) acc[m][n][q] = 0.0f;

    const int bBase = tig * B_ROW + wn * 32 + gid;      // float idx

    int slot = 0, cph = 0;
#pragma unroll 1
    for (int i = 0; i < KITERS; i++) {
        __syncthreads();   // all warps done reading slot (i-1)%3 == (i+2)%3
        if (i + 2 < KITERS && wid == 0)
            bulk_fill(i + 2, (slot == 0) ? 2 : slot - 1);
        MBARRIER_WAIT_PARITY(sb + SM_MBARF + slot * 8, cph);

        const float* Ast = As + slot * (A_ST / 4);
        const float* Bst = Bs + slot * (B_ST / 4);
#pragma unroll
        for (int kb = 0; kb < 4; kb++) {
            uint4 av[4];
#pragma unroll
            for (int m = 0; m < 4; m++)
                av[m] = *(const uint4*)(Ast + (((wm * 4 + m) * 4 + kb) * 32 + lane) * 4);
            uint32_t b0[4], b1[4];
#pragma unroll
            for (int n = 0; n < 4; n++) {
                const float* p = Bst + kb * (8 * B_ROW) + bBase + n * 8;
                b0[n] = f2tf(p[0]);
                b1[n] = f2tf(p[4 * B_ROW]);
            }
#pragma unroll
            for (int m = 0; m < 4; m++)
#pragma unroll
                for (int n = 0; n < 4; n++)
                    mma8(acc[m][n], (const uint32_t*)&av[m], b0[n], b1[n]);
        }
        slot++;
        if (slot == STAGES) { slot = 0; cph ^= 1; }
    }

    // ---- epilogue: add bias, scatter rows ----
#pragma unroll
    for (int m = 0; m < 4; m++) {
        int r0 = wm * 64 + m * 16 + gid;
        int ra = rows[r0], rb = rows[r0 + 8];
#pragma unroll
        for (int n = 0; n < 4; n++) {
            int lc = wn * 32 + n * 8 + tig * 2;
            float bv0 = bsm[lc], bv1 = bsm[lc + 1];
            if (ra >= 0) {
                float2 v = make_float2(acc[m][n][0] + bv0, acc[m][n][1] + bv1);
                *(float2*)(out + (size_t)ra * NDIM + n0 + lc) = v;
            }
            if (rb >= 0) {
                float2 v = make_float2(acc[m][n][2] + bv0, acc[m][n][3] + bv1);
                *(float2*)(out + (size_t)rb * NDIM + n0 + lc) = v;
            }
        }
    }
}

extern "C" void kernel_launch(void* const* d_in, const int* in_sizes, int n_in,
                              void* d_out, int out_size) {
    const float* x = (const float*)d_in[0];
    const int* sid = (const int*)d_in[1];
    const float* w = (const float*)d_in[2];
    const float* b = (const float*)d_in[3];
    float* out = (float*)d_out;

    cudaFuncSetAttribute(gemm_kernel,
                         cudaFuncAttributeMaxDynamicSharedMemorySize, SMEM_BYTES);
    bucket_kernel<<<1, 1024>>>(sid);
    dim3 ggrid(KITERS, MAXMT);
    gather_kernel<<<ggrid, 1024>>>(x);
    dim3 grid(NT_N, MAXMT);
    gemm_kernel<<<grid, NTHR, SMEM_BYTES>>>(w, b, out);
}